// round 8
// baseline (speedup 1.0000x reference)
#include <cuda_runtime.h>
#include <cuda_fp16.h>
#include <math.h>
#include <stdint.h>

// Problem constants
#define BMAX   16384
#define INDIM  128
#define STATE  64
#define HID    1024
#define NB     8
#define KACT   (INDIM + INDIM * NB)   // 1152
#define NOUT2  (8192 + 64)            // 8256
#define NOUT2P 8448                   // padded to multiple of 256

// ---------------- scratch ----------------
__device__ float  g_x   [BMAX * INDIM];
__device__ __half g_act [BMAX * KACT];
__device__ __half g_kan [BMAX * HID];
__device__ __half g_W1T [HID * KACT];            // [o][k]
__device__ __half g_W2T [(size_t)NOUT2P * HID];  // [n][h], zero-padded rows
__device__ float  g_b2  [NOUT2];

// ---------------- helpers ----------------
__device__ __forceinline__ void ldsm4(uint32_t addr, uint32_t& r0, uint32_t& r1,
                                      uint32_t& r2, uint32_t& r3) {
    asm volatile("ldmatrix.sync.aligned.m8n8.x4.shared.b16 {%0,%1,%2,%3}, [%4];"
                 : "=r"(r0), "=r"(r1), "=r"(r2), "=r"(r3) : "r"(addr));
}

__device__ __forceinline__ void mma_f16(float* d, const uint32_t* a, const uint32_t* b) {
    asm volatile(
        "mma.sync.aligned.m16n8k16.row.col.f32.f16.f16.f32 "
        "{%0,%1,%2,%3}, {%4,%5,%6,%7}, {%8,%9}, {%0,%1,%2,%3};"
        : "+f"(d[0]), "+f"(d[1]), "+f"(d[2]), "+f"(d[3])
        : "r"(a[0]), "r"(a[1]), "r"(a[2]), "r"(a[3]), "r"(b[0]), "r"(b[1]));
}

__device__ __forceinline__ void cpa16(uint32_t smem, const void* g) {
    asm volatile("cp.async.cg.shared.global [%0], [%1], 16;" :: "r"(smem), "l"(g));
}
__device__ __forceinline__ void cpa_commit() { asm volatile("cp.async.commit_group;"); }
__device__ __forceinline__ void cpa_wait1()  { asm volatile("cp.async.wait_group 1;"); }

// ---------------- merged prep kernel ----------------
#define NB_W2T ((NOUT2P / 32) * (HID / 32))
#define NB_W1T ((HID * KACT + 255) / 256)
#define NB_B2  ((NOUT2 + 255) / 256)

__global__ __launch_bounds__(256) void prep_all(const float* __restrict__ scale_base,
                                                const float* __restrict__ scale_sp,
                                                const float* __restrict__ coef,
                                                const float* __restrict__ f_w,
                                                const float* __restrict__ bias_w,
                                                const float* __restrict__ f_b,
                                                const float* __restrict__ bias_b) {
    int bx = blockIdx.x;
    int tid = threadIdx.x;
    if (bx < NB_W2T) {
        __shared__ float tile[32][33];
        int tileN = bx % (NOUT2P / 32), tileH = bx / (NOUT2P / 32);
        int n0 = tileN * 32, h0 = tileH * 32;
        int tx = tid & 31, ty0 = tid >> 5;
#pragma unroll
        for (int p = 0; p < 4; p++) {
            int ty = ty0 + p * 8;
            int n = n0 + tx;
            float v = 0.0f;
            if (n < 8192)       v = f_w[(size_t)(h0 + ty) * 8192 + n];
            else if (n < NOUT2) v = bias_w[(h0 + ty) * 64 + (n - 8192)];
            tile[ty][tx] = v;
        }
        __syncthreads();
#pragma unroll
        for (int p = 0; p < 4; p++) {
            int ty = ty0 + p * 8;
            g_W2T[(size_t)(n0 + ty) * HID + h0 + tx] = __float2half(tile[tx][ty]);
        }
    } else if (bx < NB_W2T + NB_W1T) {
        int idx = (bx - NB_W2T) * 256 + tid;
        if (idx >= HID * KACT) return;
        int o = idx / KACT, k = idx - o * KACT;
        float v;
        if (k < INDIM) {
            v = scale_base[k * HID + o];
        } else {
            int kk = k - INDIM;
            int i = kk >> 3, c = kk & 7;
            v = scale_sp[i * HID + o] * coef[(i * HID + o) * NB + c];
        }
        g_W1T[idx] = __float2half(v);
    } else {
        int idx = (bx - NB_W2T - NB_W1T) * 256 + tid;
        if (idx >= NOUT2) return;
        g_b2[idx] = (idx < 8192) ? f_b[idx] : bias_b[idx - 8192];
    }
}

// ---------------- activation build ----------------
__device__ __forceinline__ float knot(int j) { return -1.0f + 0.4f * (float)(j - 3); }

__global__ void build_act(const float* __restrict__ state,
                          const float* __restrict__ novelU, int B) {
    int idx = blockIdx.x * blockDim.x + threadIdx.x;
    if (idx >= B * INDIM) return;
    int b = idx / INDIM, i = idx - b * INDIM;
    float x = (i < STATE) ? state[b * STATE + i] : novelU[b * (INDIM - STATE) + (i - STATE)];
    g_x[b * INDIM + i] = x;
    g_act[(size_t)b * KACT + i] = __float2half(x / (1.0f + expf(-x)));
    float bb[11];
#pragma unroll
    for (int j = 0; j < 11; j++)
        bb[j] = (x >= knot(j) && x < knot(j + 1)) ? 1.0f : 0.0f;
#pragma unroll
    for (int ord = 1; ord <= 3; ord++) {
#pragma unroll
        for (int j = 0; j < 11 - 1; j++) {
            if (j >= 11 - ord) break;
            float l = (x - knot(j)) / (knot(j + ord) - knot(j));
            float r = (knot(j + ord + 1) - x) / (knot(j + ord + 1) - knot(j + 1));
            bb[j] = l * bb[j] + r * bb[j + 1];
        }
    }
    __half2 h0 = __floats2half2_rn(bb[0], bb[1]);
    __half2 h1 = __floats2half2_rn(bb[2], bb[3]);
    __half2 h2 = __floats2half2_rn(bb[4], bb[5]);
    __half2 h3 = __floats2half2_rn(bb[6], bb[7]);
    uint4 pack = make_uint4(*(uint32_t*)&h0, *(uint32_t*)&h1, *(uint32_t*)&h2, *(uint32_t*)&h3);
    *(uint4*)&g_act[(size_t)b * KACT + INDIM + i * NB] = pack;
}

// ---------------- FP16 tensor-core GEMM ------------------------------------
// CTA tile 128x256, 512 threads, KC=64, 3-stage cp.async ring,
// intra-chunk fragment double-buffering (ldsm of ks+1 overlaps MMA of ks).
#define KC    64
#define SAH   72
#define STG_H ((128 + 256) * SAH)
#define STGB  (STG_H * 2)
#define XSP   130

template<int K, bool EPI2>
__global__ __launch_bounds__(512) void mma_gemm(const __half* __restrict__ A,
                                                const __half* __restrict__ Bt,
                                                __half* __restrict__ C,
                                                float* __restrict__ outAB,
                                                float* __restrict__ outBias,
                                                float* __restrict__ outO) {
    extern __shared__ char dynsmem[];
    uint32_t smem_addr = (uint32_t)__cvta_generic_to_shared(dynsmem);

    int tid = threadIdx.x;
    int lane = tid & 31, wid = tid >> 5;
    int row0 = blockIdx.y * 128, col0 = blockIdx.x * 256;
    int m0w = (wid & 1) * 64;
    int n0w = (wid >> 1) * 32;

    int rowA = lane & 15;
    int kAh  = 8 * (lane >> 4);
    int rowB = (lane & 7) + 8 * (lane >> 4);
    int kBh  = 8 * ((lane >> 3) & 1);

    float acc[4][4][4];
#pragma unroll
    for (int mt = 0; mt < 4; mt++)
#pragma unroll
        for (int nt = 0; nt < 4; nt++)
#pragma unroll
            for (int j = 0; j < 4; j++) acc[mt][nt][j] = 0.0f;

    const int nk = K / KC;

    auto load_stage = [&](int stg, int k0) {
        uint32_t base = smem_addr + stg * STGB;
#pragma unroll
        for (int c = 0; c < 6; c++) {
            int ch  = tid + c * 512;
            int r   = ch >> 3;
            int off = (ch & 7) * 8;
            const __half* src = (r < 128)
                ? A  + (size_t)(row0 + r) * K + k0 + off
                : Bt + (size_t)(col0 + (r - 128)) * K + k0 + off;
            cpa16(base + (uint32_t)(r * SAH + off) * 2, src);
        }
    };

    load_stage(0, 0);
    cpa_commit();
    load_stage(1, KC);
    cpa_commit();

    uint32_t a[2][4][4], b[2][2][4];

    for (int it = 0; it < nk; it++) {
        int cur = it % 3;
        cpa_wait1();
        __syncthreads();
        int nx = it + 2;
        if (nx < nk) load_stage(nx % 3, nx * KC);
        cpa_commit();

        uint32_t sA = smem_addr + cur * STGB;
        uint32_t sB = sA + 128 * SAH * 2;

        // prologue: fragments for ks=0
#pragma unroll
        for (int mt = 0; mt < 4; mt++) {
            uint32_t addr = sA + (uint32_t)((m0w + mt * 16 + rowA) * SAH + kAh) * 2;
            ldsm4(addr, a[0][mt][0], a[0][mt][1], a[0][mt][2], a[0][mt][3]);
        }
#pragma unroll
        for (int ng = 0; ng < 2; ng++) {
            uint32_t addr = sB + (uint32_t)((n0w + ng * 16 + rowB) * SAH + kBh) * 2;
            ldsm4(addr, b[0][ng][0], b[0][ng][1], b[0][ng][2], b[0][ng][3]);
        }

#pragma unroll
        for (int ks = 0; ks < 4; ks++) {
            int bufc = ks & 1, bufn = bufc ^ 1;
            if (ks < 3) {
                int kh = (ks + 1) * 16;
#pragma unroll
                for (int mt = 0; mt < 4; mt++) {
                    uint32_t addr = sA + (uint32_t)((m0w + mt * 16 + rowA) * SAH + kh + kAh) * 2;
                    ldsm4(addr, a[bufn][mt][0], a[bufn][mt][1], a[bufn][mt][2], a[bufn][mt][3]);
                }
#pragma unroll
                for (int ng = 0; ng < 2; ng++) {
                    uint32_t addr = sB + (uint32_t)((n0w + ng * 16 + rowB) * SAH + kh + kBh) * 2;
                    ldsm4(addr, b[bufn][ng][0], b[bufn][ng][1], b[bufn][ng][2], b[bufn][ng][3]);
                }
            }
#pragma unroll
            for (int mt = 0; mt < 4; mt++)
#pragma unroll
                for (int nt = 0; nt < 4; nt++)
                    mma_f16(acc[mt][nt], a[bufc][mt], &b[bufc][nt >> 1][(nt & 1) * 2]);
        }
    }

    int gid = lane >> 2, tig = lane & 3;

    // ---- matrix stores ----
#pragma unroll
    for (int mt = 0; mt < 4; mt++) {
#pragma unroll
        for (int nt = 0; nt < 4; nt++) {
            int r0r = row0 + m0w + mt * 16 + gid;
            int n   = col0 + n0w + nt * 8 + 2 * tig;
            if (!EPI2) {
                __half2 v01 = __floats2half2_rn(acc[mt][nt][0], acc[mt][nt][1]);
                __half2 v23 = __floats2half2_rn(acc[mt][nt][2], acc[mt][nt][3]);
                *(__half2*)(C + (size_t)r0r * HID + n)       = v01;
                *(__half2*)(C + (size_t)(r0r + 8) * HID + n) = v23;
            } else {
                if (n >= NOUT2) continue;
                float b0 = g_b2[n], b1 = g_b2[n + 1];
                float2 v01 = make_float2(acc[mt][nt][0] + b0, acc[mt][nt][1] + b1);
                float2 v23 = make_float2(acc[mt][nt][2] + b0, acc[mt][nt][3] + b1);
                if (n < 8192) {
                    *(float2*)(outAB + (size_t)r0r * 8192 + n)       = v01;
                    *(float2*)(outAB + (size_t)(r0r + 8) * 8192 + n) = v23;
                } else {
                    int nb = n - 8192;
                    *(float2*)(outBias + (size_t)r0r * 64 + nb)       = v01;
                    *(float2*)(outBias + (size_t)(r0r + 8) * 64 + nb) = v23;
                }
            }
        }
    }

    // ---- fused out = (AB + f_b tile) . x ; 256-col tile = 2 s values ----
    if (EPI2 && col0 < 8192) {
        float* xs  = (float*)dynsmem;
        float* red = xs + 128 * XSP;
        __syncthreads();
        for (int i = tid * 4; i < 128 * 128; i += 512 * 4) {
            int r = i >> 7, u = i & 127;
            float4 v = *(const float4*)(g_x + (size_t)(row0 + r) * INDIM + u);
            xs[r * XSP + u]     = v.x;
            xs[r * XSP + u + 1] = v.y;
            xs[r * XSP + u + 2] = v.z;
            xs[r * XSP + u + 3] = v.w;
        }
        __syncthreads();

        int g = wid >> 1;
        int sl = g >> 2;
        int jj = g & 3;
#pragma unroll
        for (int mt = 0; mt < 4; mt++) {
            int lr = m0w + mt * 16 + gid;
            float p0 = 0.0f, p1 = 0.0f;
#pragma unroll
            for (int nt = 0; nt < 4; nt++) {
                int u  = n0w + nt * 8 + 2 * tig;
                int ux = u & 127;
                float n_b0 = g_b2[col0 + u], n_b1 = g_b2[col0 + u + 1];
                float x00 = xs[lr * XSP + ux],       x01 = xs[lr * XSP + ux + 1];
                float x10 = xs[(lr + 8) * XSP + ux], x11 = xs[(lr + 8) * XSP + ux + 1];
                p0 = fmaf(acc[mt][nt][0] + n_b0, x00, p0);
                p0 = fmaf(acc[mt][nt][1] + n_b1, x01, p0);
                p1 = fmaf(acc[mt][nt][2] + n_b0, x10, p1);
                p1 = fmaf(acc[mt][nt][3] + n_b1, x11, p1);
            }
            p0 += __shfl_xor_sync(0xffffffff, p0, 1);
            p0 += __shfl_xor_sync(0xffffffff, p0, 2);
            p1 += __shfl_xor_sync(0xffffffff, p1, 1);
            p1 += __shfl_xor_sync(0xffffffff, p1, 2);
            if (tig == 0) {
                red[(jj * 2 + sl) * 128 + lr]     = p0;
                red[(jj * 2 + sl) * 128 + lr + 8] = p1;
            }
        }
        __syncthreads();
        if (tid < 256) {
            int srow = tid & 127, s_l = tid >> 7;
            float v = red[(0 * 2 + s_l) * 128 + srow] + red[(1 * 2 + s_l) * 128 + srow]
                    + red[(2 * 2 + s_l) * 128 + srow] + red[(3 * 2 + s_l) * 128 + srow];
            outO[(size_t)(row0 + srow) * 64 + (col0 >> 7) + s_l] = v;
        }
    }
}

// ---------------- out += bias ----------------
__global__ void add_bias(const float* __restrict__ biasOut, float* __restrict__ outO, int n) {
    int i = blockIdx.x * blockDim.x + threadIdx.x;
    if (i < n) outO[i] += biasOut[i];
}

// ---------------- launch ----------------
extern "C" void kernel_launch(void* const* d_in, const int* in_sizes, int n_in,
                              void* d_out, int out_size) {
    const float* novelU     = (const float*)d_in[0];
    const float* state      = (const float*)d_in[1];
    const float* coef       = (const float*)d_in[2];
    const float* scale_base = (const float*)d_in[3];
    const float* scale_sp   = (const float*)d_in[4];
    const float* bias_w     = (const float*)d_in[5];
    const float* bias_b     = (const float*)d_in[6];
    const float* f_w        = (const float*)d_in[7];
    const float* f_b        = (const float*)d_in[8];
    float* out = (float*)d_out;

    int B = in_sizes[0] / 64;
    if (B > BMAX) B = BMAX;

    float* outO    = out;
    float* outAB   = out + (size_t)B * 64;
    float* outBias = out + (size_t)B * 64 + (size_t)B * 8192;

    prep_all<<<NB_W2T + NB_W1T + NB_B2, 256>>>(scale_base, scale_sp, coef,
                                               f_w, bias_w, f_b, bias_b);
    build_act<<<(B * INDIM + 255) / 256, 256>>>(state, novelU, B);

    __half *d_kan, *d_act, *d_W1T, *d_W2T;
    cudaGetSymbolAddress((void**)&d_kan, g_kan);
    cudaGetSymbolAddress((void**)&d_act, g_act);
    cudaGetSymbolAddress((void**)&d_W1T, g_W1T);
    cudaGetSymbolAddress((void**)&d_W2T, g_W2T);

    const int smem_stage = 3 * STGB;
    const int smem_epi   = 128 * XSP * 4 + 8 * 128 * 4;
    const int smem_bytes = smem_epi > smem_stage ? smem_epi : smem_stage;
    static bool attr_set = false;
    if (!attr_set) {
        cudaFuncSetAttribute(mma_gemm<KACT, false>,
                             cudaFuncAttributeMaxDynamicSharedMemorySize, smem_bytes);
        cudaFuncSetAttribute(mma_gemm<HID, true>,
                             cudaFuncAttributeMaxDynamicSharedMemorySize, smem_bytes);
        attr_set = true;
    }

    dim3 g1(HID / 256, B / 128);
    mma_gemm<KACT, false><<<g1, 512, smem_bytes>>>(d_act, d_W1T, d_kan, nullptr, nullptr, nullptr);

    dim3 g2(NOUT2P / 256, B / 128);
    mma_gemm<HID, true><<<g2, 512, smem_bytes>>>(d_kan, d_W2T, nullptr, outAB, outBias, outO);

    add_bias<<<(B * 64 + 255) / 256, 256>>>(outBias, outO, B * 64);
}